// round 5
// baseline (speedup 1.0000x reference)
#include <cuda_runtime.h>
#include <cuda_fp16.h>
#include <cstdint>

#define N_NODES 50000
#define N_EDGES 800000
#define C 32
#define BN_EPS 1e-5f

typedef unsigned long long ull;

// ---------------- device scratch ----------------
__device__ __align__(16) float g_A[N_NODES * C];
__device__ __align__(16) float g_B[N_NODES * C];
__device__ __align__(16) __half g_y2h[(size_t)N_EDGES * C]; // 51.2 MB (fp16, edge order)
__device__ float g_stat1[64];
__device__ float g_stat2[64];
__device__ int g_off[N_NODES + 1];   // CSR offsets (by source node)
__device__ int g_cur[N_NODES];       // fill cursors
__device__ int g_perm[N_EDGES];      // CSR-ordered edge ids

__device__ __forceinline__ ull pack2(float lo, float hi) {
    ull r; asm("mov.b64 %0, {%1, %2};" : "=l"(r) : "f"(lo), "f"(hi)); return r;
}
__device__ __forceinline__ float2 unpack2(ull v) {
    float2 f; asm("mov.b64 {%0, %1}, %2;" : "=f"(f.x), "=f"(f.y) : "l"(v)); return f;
}
__device__ __forceinline__ ull fma2(ull a, ull b, ull c) {
    ull d; asm("fma.rn.f32x2 %0, %1, %2, %3;" : "=l"(d) : "l"(a), "l"(b), "l"(c)); return d;
}

// ---------------- K1: zero stats/hist + per-node precompute ----------------
__global__ void k1_node(const float* __restrict__ x, const float* __restrict__ W1,
                        const float* __restrict__ b1) {
    int g = blockIdx.x * blockDim.x + threadIdx.x;
    if (g < 64) { g_stat1[g] = 0.f; g_stat2[g] = 0.f; }
    if (g <= N_NODES) g_off[g] = 0;

    __shared__ float sW[2 * C * C];
    for (int i = threadIdx.x; i < 2 * C * C; i += blockDim.x) sW[i] = W1[i];
    __syncthreads();
    int warp = threadIdx.x >> 5, lane = threadIdx.x & 31;
    int node = blockIdx.x * (blockDim.x >> 5) + warp;
    if (node >= N_NODES) return;
    float xv = x[node * C + lane];
    float a = b1[lane], b = 0.f;
#pragma unroll
    for (int i = 0; i < C; i++) {
        float xi = __shfl_sync(0xffffffffu, xv, i);
        a = fmaf(xi, sW[i * C + lane], a);
        b = fmaf(xi, sW[(i + C) * C + lane], b);
    }
    g_A[node * C + lane] = a;
    g_B[node * C + lane] = b;
}

// ---------------- CSR build: histogram, prefix scan, permutation ----------
__global__ void khist(const int* __restrict__ ei) {
    int e = blockIdx.x * blockDim.x + threadIdx.x;
    atomicAdd(&g_off[ei[e] + 1], 1);
}

__global__ void kprefix() { // single block, 1024 threads; inclusive scan of g_off
    const int CH = 49; // 1024*49 = 50176 >= 50001
    int t = threadIdx.x;
    int base = t * CH;
    int s = 0;
    for (int i = 0; i < CH; i++) {
        int idx = base + i;
        if (idx <= N_NODES) s += g_off[idx];
    }
    int lane = t & 31, warp = t >> 5;
    int v = s;
#pragma unroll
    for (int off = 1; off < 32; off <<= 1) {
        int u = __shfl_up_sync(0xffffffffu, v, off);
        if (lane >= off) v += u;
    }
    __shared__ int ws[32];
    if (lane == 31) ws[warp] = v;
    __syncthreads();
    if (warp == 0) {
        int w = ws[lane];
#pragma unroll
        for (int off = 1; off < 32; off <<= 1) {
            int u = __shfl_up_sync(0xffffffffu, w, off);
            if (lane >= off) w += u;
        }
        ws[lane] = w;
    }
    __syncthreads();
    int run = v - s + (warp ? ws[warp - 1] : 0); // exclusive prefix of chunk
    for (int i = 0; i < CH; i++) {
        int idx = base + i;
        if (idx <= N_NODES) {
            run += g_off[idx];
            g_off[idx] = run;
            if (idx < N_NODES) g_cur[idx] = run;
        }
    }
}

__global__ void kperm(const int* __restrict__ ei) {
    int e = blockIdx.x * blockDim.x + threadIdx.x;
    int pos = atomicAdd(&g_cur[ei[e]], 1);
    g_perm[pos] = e;
}

// ---------------- K2: per-channel sum/sumsq of y1 = A[row]+B[col] ----------
__global__ void k2_stats1(const int* __restrict__ ei) {
    int g = blockIdx.x * blockDim.x + threadIdx.x;
    int nthr = gridDim.x * blockDim.x;
    int chunk = g & 3;
    float s[8], q[8];
#pragma unroll
    for (int i = 0; i < 8; i++) { s[i] = 0.f; q[i] = 0.f; }
    const float4* A4 = (const float4*)g_A;
    const float4* B4 = (const float4*)g_B;
    for (int e = g >> 2; e < N_EDGES; e += nthr >> 2) {
        int row = ei[e];
        int col = ei[N_EDGES + e];
        float4 a0 = A4[row * 8 + chunk * 2], a1 = A4[row * 8 + chunk * 2 + 1];
        float4 b0 = B4[col * 8 + chunk * 2], b1 = B4[col * 8 + chunk * 2 + 1];
        float y;
        y = a0.x + b0.x; s[0] += y; q[0] = fmaf(y, y, q[0]);
        y = a0.y + b0.y; s[1] += y; q[1] = fmaf(y, y, q[1]);
        y = a0.z + b0.z; s[2] += y; q[2] = fmaf(y, y, q[2]);
        y = a0.w + b0.w; s[3] += y; q[3] = fmaf(y, y, q[3]);
        y = a1.x + b1.x; s[4] += y; q[4] = fmaf(y, y, q[4]);
        y = a1.y + b1.y; s[5] += y; q[5] = fmaf(y, y, q[5]);
        y = a1.z + b1.z; s[6] += y; q[6] = fmaf(y, y, q[6]);
        y = a1.w + b1.w; s[7] += y; q[7] = fmaf(y, y, q[7]);
    }
#pragma unroll
    for (int off = 4; off < 32; off <<= 1) {
#pragma unroll
        for (int i = 0; i < 8; i++) {
            s[i] += __shfl_xor_sync(0xffffffffu, s[i], off);
            q[i] += __shfl_xor_sync(0xffffffffu, q[i], off);
        }
    }
    __shared__ float sh[64];
    if (threadIdx.x < 64) sh[threadIdx.x] = 0.f;
    __syncthreads();
    int lane = threadIdx.x & 31;
    if (lane < 4) {
#pragma unroll
        for (int i = 0; i < 8; i++) {
            atomicAdd(&sh[chunk * 8 + i], s[i]);
            atomicAdd(&sh[32 + chunk * 8 + i], q[i]);
        }
    }
    __syncthreads();
    if (threadIdx.x < 64) atomicAdd(&g_stat1[threadIdx.x], sh[threadIdx.x]);
}

// ---------------- K4: gather -> SMEM -> 2-edge GEMM + fused stats2 ---------
#define HS 33  // padded h-tile stride (floats)
__global__ void __launch_bounds__(128, 4) k4_main(const int* __restrict__ ei,
                                                  const float* __restrict__ W2,
                                                  const float* __restrict__ b2,
                                                  const float* __restrict__ gamma1,
                                                  const float* __restrict__ beta1) {
    __shared__ __align__(16) float sW2[C * C];
    __shared__ float sh_h[256 * HS]; // phase1/2: h tile; epilogue: stats transpose
    __shared__ float sS1[C], sT1[C], sB2[C];
    int tid = threadIdx.x;
    for (int i = tid; i < C * C; i += blockDim.x) sW2[i] = W2[i];
    if (tid < C) {
        const float invE = 1.f / (float)N_EDGES;
        float mean = g_stat1[tid] * invE;
        float var = g_stat1[32 + tid] * invE - mean * mean;
        float s = gamma1[tid] * rsqrtf(var + BN_EPS);
        sS1[tid] = s;
        sT1[tid] = beta1[tid] - mean * s;
        sB2[tid] = b2[tid];
    }
    __syncthreads();

    // ---- phase 1: coalesced gather + BN1 + ReLU -> fp32 SMEM tile ----
    int q = tid & 3;
    const float4* A4 = (const float4*)g_A;
    const float4* B4 = (const float4*)g_B;
    float s1v[8], t1v[8];
#pragma unroll
    for (int j = 0; j < 8; j++) { s1v[j] = sS1[q * 8 + j]; t1v[j] = sT1[q * 8 + j]; }
#pragma unroll
    for (int r = 0; r < 8; r++) {
        int el = (tid >> 2) + r * 32;
        int e = blockIdx.x * 256 + el;
        int row = ei[e];
        int col = ei[N_EDGES + e];
        float4 a0 = A4[row * 8 + q * 2], a1 = A4[row * 8 + q * 2 + 1];
        float4 b0 = B4[col * 8 + q * 2], b1 = B4[col * 8 + q * 2 + 1];
        float* hrow = sh_h + el * HS + q * 8;
        hrow[0] = fmaxf(fmaf(a0.x + b0.x, s1v[0], t1v[0]), 0.f);
        hrow[1] = fmaxf(fmaf(a0.y + b0.y, s1v[1], t1v[1]), 0.f);
        hrow[2] = fmaxf(fmaf(a0.z + b0.z, s1v[2], t1v[2]), 0.f);
        hrow[3] = fmaxf(fmaf(a0.w + b0.w, s1v[3], t1v[3]), 0.f);
        hrow[4] = fmaxf(fmaf(a1.x + b1.x, s1v[4], t1v[4]), 0.f);
        hrow[5] = fmaxf(fmaf(a1.y + b1.y, s1v[5], t1v[5]), 0.f);
        hrow[6] = fmaxf(fmaf(a1.z + b1.z, s1v[6], t1v[6]), 0.f);
        hrow[7] = fmaxf(fmaf(a1.w + b1.w, s1v[7], t1v[7]), 0.f);
    }
    __syncthreads();

    // ---- phase 2: 2 edges per thread, f32x2 GEMM ----
    ull accA[16], accB[16];
#pragma unroll
    for (int p = 0; p < 16; p++) {
        ull init = pack2(sB2[2 * p], sB2[2 * p + 1]);
        accA[p] = init; accB[p] = init;
    }
    const ulonglong2* W16 = (const ulonglong2*)sW2;
    const float* hA = sh_h + tid * HS;
    const float* hB = sh_h + (tid + 128) * HS;
#pragma unroll
    for (int i = 0; i < C; i++) {
        ull ha = pack2(hA[i], hA[i]);
        ull hb = pack2(hB[i], hB[i]);
#pragma unroll
        for (int qq = 0; qq < 8; qq++) {
            ulonglong2 w = W16[i * 8 + qq];
            accA[2 * qq]     = fma2(ha, w.x, accA[2 * qq]);
            accA[2 * qq + 1] = fma2(ha, w.y, accA[2 * qq + 1]);
            accB[2 * qq]     = fma2(hb, w.x, accB[2 * qq]);
            accB[2 * qq + 1] = fma2(hb, w.y, accB[2 * qq + 1]);
        }
    }

    // ---- store y2 (fp16) + per-thread stats ----
    float s[32], sq[32];
    uint4 ovA[4], ovB[4];
    unsigned* owA = (unsigned*)ovA;
    unsigned* owB = (unsigned*)ovB;
#pragma unroll
    for (int p = 0; p < 16; p++) {
        float2 fA = unpack2(accA[p]);
        float2 fB = unpack2(accB[p]);
        __half2 hhA = __floats2half2_rn(fA.x, fA.y);
        __half2 hhB = __floats2half2_rn(fB.x, fB.y);
        owA[p] = *(unsigned*)&hhA;
        owB[p] = *(unsigned*)&hhB;
        s[2 * p]      = fA.x + fB.x;
        s[2 * p + 1]  = fA.y + fB.y;
        sq[2 * p]     = fmaf(fA.x, fA.x, fB.x * fB.x);
        sq[2 * p + 1] = fmaf(fA.y, fA.y, fB.y * fB.y);
    }
    size_t gA = (size_t)blockIdx.x * 256 + tid;
    size_t gB = gA + 128;
    uint4* Y = (uint4*)g_y2h;
#pragma unroll
    for (int p = 0; p < 4; p++) { Y[gA * 4 + p] = ovA[p]; Y[gB * 4 + p] = ovB[p]; }

    // ---- stats2 reduce via SMEM transpose (reuse sh_h; stride 65) ----
    __syncthreads(); // all sh_h reads done
    float* T = sh_h; // [128][65] view: 8320 <= 8448 floats
#pragma unroll
    for (int j = 0; j < 32; j++) {
        T[tid * 65 + j] = s[j];
        T[tid * 65 + 32 + j] = sq[j];
    }
    __syncthreads();
    if (tid < 64) {
        float v = 0.f;
#pragma unroll 8
        for (int r = 0; r < 128; r++) v += T[r * 65 + tid];
        atomicAdd(&g_stat2[tid], v);
    }
}

// ---------------- K7: CSR gather: warp per node, no atomics ----------------
__global__ void __launch_bounds__(256) k7_csr(const float* __restrict__ gamma2,
                                              const float* __restrict__ beta2,
                                              float* __restrict__ out) {
    __shared__ float sS2[C], sT2[C];
    if (threadIdx.x < C) {
        int c = threadIdx.x;
        const float invE = 1.f / (float)N_EDGES;
        float mean = g_stat2[c] * invE;
        float var = g_stat2[32 + c] * invE - mean * mean;
        float s = gamma2[c] * rsqrtf(var + BN_EPS);
        sS2[c] = s;
        sT2[c] = beta2[c] - mean * s;
    }
    __syncthreads();
    int warp = threadIdx.x >> 5, lane = threadIdx.x & 31;
    int n = blockIdx.x * 8 + warp; // grid*8 = 50000 exact
    int start = g_off[n], end = g_off[n + 1];
    int w = lane & 15, half = lane >> 4;
    float sx = sS2[2 * w], sy = sS2[2 * w + 1];
    float tx = sT2[2 * w], ty = sT2[2 * w + 1];
    float ax = 0.f, ay = 0.f;
    const unsigned* Y = (const unsigned*)g_y2h; // 16 uints per edge row
    for (int p = start + half; p < end; p += 2) {
        int eid = g_perm[p];
        unsigned v = Y[(size_t)eid * 16 + w];
        float2 f = __half22float2(*(const __half2*)&v);
        ax += fmaxf(fmaf(f.x, sx, tx), 0.f);
        ay += fmaxf(fmaf(f.y, sy, ty), 0.f);
    }
    ax += __shfl_xor_sync(0xffffffffu, ax, 16);
    ay += __shfl_xor_sync(0xffffffffu, ay, 16);
    if (half == 0) {
        float2* o = (float2*)out;
        o[n * 16 + w] = make_float2(ax, ay);
    }
}

// ---------------- launch ----------------------------------------------------
extern "C" void kernel_launch(void* const* d_in, const int* in_sizes, int n_in,
                              void* d_out, int out_size) {
    const float* x      = (const float*)d_in[0];
    const float* W1     = (const float*)d_in[1];
    const float* b1     = (const float*)d_in[2];
    const float* gamma1 = (const float*)d_in[3];
    const float* beta1  = (const float*)d_in[4];
    const float* W2     = (const float*)d_in[5];
    const float* b2     = (const float*)d_in[6];
    const float* gamma2 = (const float*)d_in[7];
    const float* beta2  = (const float*)d_in[8];
    const int* ei       = (const int*)d_in[9];
    float* out = (float*)d_out;

    k1_node<<<N_NODES / 8, 256>>>(x, W1, b1);          // 6250 blocks
    khist<<<N_EDGES / 256, 256>>>(ei);
    kprefix<<<1, 1024>>>();
    kperm<<<N_EDGES / 256, 256>>>(ei);
    k2_stats1<<<2048, 256>>>(ei);
    k4_main<<<N_EDGES / 256, 128>>>(ei, W2, b2, gamma1, beta1);
    k7_csr<<<N_NODES / 8, 256>>>(gamma2, beta2, out);
}

// round 6
// speedup vs baseline: 1.0755x; 1.0755x over previous
#include <cuda_runtime.h>
#include <cuda_fp16.h>
#include <cstdint>

#define N_NODES 50000
#define N_EDGES 800000
#define C 32
#define BN_EPS 1e-5f

typedef unsigned long long ull;

// ---------------- device scratch ----------------
__device__ __align__(16) float g_A[N_NODES * C];
__device__ __align__(16) float g_B[N_NODES * C];
__device__ __align__(16) __half g_y2h[(size_t)N_EDGES * C]; // 51.2 MB fp16, CSR order
__device__ float g_stat1[64];
__device__ float g_stat2[64];
__device__ int g_off[N_NODES + 1];   // CSR offsets (by source node)
__device__ int g_cur[N_NODES];       // fill cursors

__device__ __forceinline__ ull pack2(float lo, float hi) {
    ull r; asm("mov.b64 %0, {%1, %2};" : "=l"(r) : "f"(lo), "f"(hi)); return r;
}
__device__ __forceinline__ float2 unpack2(ull v) {
    float2 f; asm("mov.b64 {%0, %1}, %2;" : "=f"(f.x), "=f"(f.y) : "l"(v)); return f;
}
__device__ __forceinline__ ull fma2(ull a, ull b, ull c) {
    ull d; asm("fma.rn.f32x2 %0, %1, %2, %3;" : "=l"(d) : "l"(a), "l"(b), "l"(c)); return d;
}

// ---------------- K1: zero stats/hist + per-node precompute ----------------
__global__ void k1_node(const float* __restrict__ x, const float* __restrict__ W1,
                        const float* __restrict__ b1) {
    int g = blockIdx.x * blockDim.x + threadIdx.x;
    if (g < 64) { g_stat1[g] = 0.f; g_stat2[g] = 0.f; }
    if (g <= N_NODES) g_off[g] = 0;

    __shared__ float sW[2 * C * C];
    for (int i = threadIdx.x; i < 2 * C * C; i += blockDim.x) sW[i] = W1[i];
    __syncthreads();
    int warp = threadIdx.x >> 5, lane = threadIdx.x & 31;
    int node = blockIdx.x * (blockDim.x >> 5) + warp;
    if (node >= N_NODES) return;
    float xv = x[node * C + lane];
    float a = b1[lane], b = 0.f;
#pragma unroll
    for (int i = 0; i < C; i++) {
        float xi = __shfl_sync(0xffffffffu, xv, i);
        a = fmaf(xi, sW[i * C + lane], a);
        b = fmaf(xi, sW[(i + C) * C + lane], b);
    }
    g_A[node * C + lane] = a;
    g_B[node * C + lane] = b;
}

// ---------------- K2: stats1 of y1 = A[row]+B[col]  (+ degree histogram) ---
__global__ void k2_stats1(const int* __restrict__ ei) {
    int g = blockIdx.x * blockDim.x + threadIdx.x;
    int nthr = gridDim.x * blockDim.x;
    int chunk = g & 3;
    float s[8], q[8];
#pragma unroll
    for (int i = 0; i < 8; i++) { s[i] = 0.f; q[i] = 0.f; }
    const float4* A4 = (const float4*)g_A;
    const float4* B4 = (const float4*)g_B;
    for (int e = g >> 2; e < N_EDGES; e += nthr >> 2) {
        int row = ei[e];
        int col = ei[N_EDGES + e];
        if (chunk == 0) atomicAdd(&g_off[row + 1], 1);   // histogram (overlapped)
        float4 a0 = A4[row * 8 + chunk * 2], a1 = A4[row * 8 + chunk * 2 + 1];
        float4 b0 = B4[col * 8 + chunk * 2], b1 = B4[col * 8 + chunk * 2 + 1];
        float y;
        y = a0.x + b0.x; s[0] += y; q[0] = fmaf(y, y, q[0]);
        y = a0.y + b0.y; s[1] += y; q[1] = fmaf(y, y, q[1]);
        y = a0.z + b0.z; s[2] += y; q[2] = fmaf(y, y, q[2]);
        y = a0.w + b0.w; s[3] += y; q[3] = fmaf(y, y, q[3]);
        y = a1.x + b1.x; s[4] += y; q[4] = fmaf(y, y, q[4]);
        y = a1.y + b1.y; s[5] += y; q[5] = fmaf(y, y, q[5]);
        y = a1.z + b1.z; s[6] += y; q[6] = fmaf(y, y, q[6]);
        y = a1.w + b1.w; s[7] += y; q[7] = fmaf(y, y, q[7]);
    }
#pragma unroll
    for (int off = 4; off < 32; off <<= 1) {
#pragma unroll
        for (int i = 0; i < 8; i++) {
            s[i] += __shfl_xor_sync(0xffffffffu, s[i], off);
            q[i] += __shfl_xor_sync(0xffffffffu, q[i], off);
        }
    }
    __shared__ float sh[64];
    if (threadIdx.x < 64) sh[threadIdx.x] = 0.f;
    __syncthreads();
    int lane = threadIdx.x & 31;
    if (lane < 4) {
#pragma unroll
        for (int i = 0; i < 8; i++) {
            atomicAdd(&sh[chunk * 8 + i], s[i]);
            atomicAdd(&sh[32 + chunk * 8 + i], q[i]);
        }
    }
    __syncthreads();
    if (threadIdx.x < 64) atomicAdd(&g_stat1[threadIdx.x], sh[threadIdx.x]);
}

// ---------------- kprefix: single-block scan of g_off; init cursors --------
__global__ void kprefix() {
    const int CH = 49; // 1024*49 >= 50001
    int t = threadIdx.x;
    int base = t * CH;
    int s = 0;
    for (int i = 0; i < CH; i++) {
        int idx = base + i;
        if (idx <= N_NODES) s += g_off[idx];
    }
    int lane = t & 31, warp = t >> 5;
    int v = s;
#pragma unroll
    for (int off = 1; off < 32; off <<= 1) {
        int u = __shfl_up_sync(0xffffffffu, v, off);
        if (lane >= off) v += u;
    }
    __shared__ int ws[32];
    if (lane == 31) ws[warp] = v;
    __syncthreads();
    if (warp == 0) {
        int w = ws[lane];
#pragma unroll
        for (int off = 1; off < 32; off <<= 1) {
            int u = __shfl_up_sync(0xffffffffu, w, off);
            if (lane >= off) w += u;
        }
        ws[lane] = w;
    }
    __syncthreads();
    int run = v - s + (warp ? ws[warp - 1] : 0);
    for (int i = 0; i < CH; i++) {
        int idx = base + i;
        if (idx <= N_NODES) {
            run += g_off[idx];
            g_off[idx] = run;
            if (idx < N_NODES) g_cur[idx] = run;
        }
    }
}

// ---------------- K4: gather -> SMEM -> GEMM; CSR-ordered y2 store + stats2
#define HS 33
__global__ void __launch_bounds__(128, 4) k4_main(const int* __restrict__ ei,
                                                  const float* __restrict__ W2,
                                                  const float* __restrict__ b2,
                                                  const float* __restrict__ gamma1,
                                                  const float* __restrict__ beta1) {
    __shared__ __align__(16) float sW2[C * C];
    __shared__ float sh_h[256 * HS];
    __shared__ float sS1[C], sT1[C], sB2[C];
    int tid = threadIdx.x;
    for (int i = tid; i < C * C; i += blockDim.x) sW2[i] = W2[i];
    if (tid < C) {
        const float invE = 1.f / (float)N_EDGES;
        float mean = g_stat1[tid] * invE;
        float var = g_stat1[32 + tid] * invE - mean * mean;
        float s = gamma1[tid] * rsqrtf(var + BN_EPS);
        sS1[tid] = s;
        sT1[tid] = beta1[tid] - mean * s;
        sB2[tid] = b2[tid];
    }
    __syncthreads();

    // ---- phase 1: coalesced gather + BN1 + ReLU -> fp32 SMEM tile ----
    int q = tid & 3;
    const float4* A4 = (const float4*)g_A;
    const float4* B4 = (const float4*)g_B;
    float s1v[8], t1v[8];
#pragma unroll
    for (int j = 0; j < 8; j++) { s1v[j] = sS1[q * 8 + j]; t1v[j] = sT1[q * 8 + j]; }
#pragma unroll
    for (int r = 0; r < 8; r++) {
        int el = (tid >> 2) + r * 32;
        int e = blockIdx.x * 256 + el;
        int row = ei[e];
        int col = ei[N_EDGES + e];
        float4 a0 = A4[row * 8 + q * 2], a1 = A4[row * 8 + q * 2 + 1];
        float4 b0 = B4[col * 8 + q * 2], b1 = B4[col * 8 + q * 2 + 1];
        float* hrow = sh_h + el * HS + q * 8;
        hrow[0] = fmaxf(fmaf(a0.x + b0.x, s1v[0], t1v[0]), 0.f);
        hrow[1] = fmaxf(fmaf(a0.y + b0.y, s1v[1], t1v[1]), 0.f);
        hrow[2] = fmaxf(fmaf(a0.z + b0.z, s1v[2], t1v[2]), 0.f);
        hrow[3] = fmaxf(fmaf(a0.w + b0.w, s1v[3], t1v[3]), 0.f);
        hrow[4] = fmaxf(fmaf(a1.x + b1.x, s1v[4], t1v[4]), 0.f);
        hrow[5] = fmaxf(fmaf(a1.y + b1.y, s1v[5], t1v[5]), 0.f);
        hrow[6] = fmaxf(fmaf(a1.z + b1.z, s1v[6], t1v[6]), 0.f);
        hrow[7] = fmaxf(fmaf(a1.w + b1.w, s1v[7], t1v[7]), 0.f);
    }
    __syncthreads();

    // ---- phase 2: 2 edges per thread, f32x2 GEMM ----
    ull accA[16], accB[16];
#pragma unroll
    for (int p = 0; p < 16; p++) {
        ull init = pack2(sB2[2 * p], sB2[2 * p + 1]);
        accA[p] = init; accB[p] = init;
    }
    const ulonglong2* W16 = (const ulonglong2*)sW2;
    const float* hA = sh_h + tid * HS;
    const float* hB = sh_h + (tid + 128) * HS;
#pragma unroll
    for (int i = 0; i < C; i++) {
        ull ha = pack2(hA[i], hA[i]);
        ull hb = pack2(hB[i], hB[i]);
#pragma unroll
        for (int qq = 0; qq < 8; qq++) {
            ulonglong2 w = W16[i * 8 + qq];
            accA[2 * qq]     = fma2(ha, w.x, accA[2 * qq]);
            accA[2 * qq + 1] = fma2(ha, w.y, accA[2 * qq + 1]);
            accB[2 * qq]     = fma2(hb, w.x, accB[2 * qq]);
            accB[2 * qq + 1] = fma2(hb, w.y, accB[2 * qq + 1]);
        }
    }

    // ---- CSR-position store (fp16) + per-thread stats ----
    int eA = blockIdx.x * 256 + tid;
    int eB = eA + 128;
    int posA = atomicAdd(&g_cur[ei[eA]], 1);
    int posB = atomicAdd(&g_cur[ei[eB]], 1);

    float s[32], sq[32];
    uint4 ovA[4], ovB[4];
    unsigned* owA = (unsigned*)ovA;
    unsigned* owB = (unsigned*)ovB;
#pragma unroll
    for (int p = 0; p < 16; p++) {
        float2 fA = unpack2(accA[p]);
        float2 fB = unpack2(accB[p]);
        __half2 hhA = __floats2half2_rn(fA.x, fA.y);
        __half2 hhB = __floats2half2_rn(fB.x, fB.y);
        owA[p] = *(unsigned*)&hhA;
        owB[p] = *(unsigned*)&hhB;
        s[2 * p]      = fA.x + fB.x;
        s[2 * p + 1]  = fA.y + fB.y;
        sq[2 * p]     = fmaf(fA.x, fA.x, fB.x * fB.x);
        sq[2 * p + 1] = fmaf(fA.y, fA.y, fB.y * fB.y);
    }
    uint4* Y = (uint4*)g_y2h;
#pragma unroll
    for (int p = 0; p < 4; p++) {
        Y[(size_t)posA * 4 + p] = ovA[p];
        Y[(size_t)posB * 4 + p] = ovB[p];
    }

    // ---- stats2 reduce via SMEM transpose (reuse sh_h; stride 65) ----
    __syncthreads();
    float* T = sh_h;
#pragma unroll
    for (int j = 0; j < 32; j++) {
        T[tid * 65 + j] = s[j];
        T[tid * 65 + 32 + j] = sq[j];
    }
    __syncthreads();
    if (tid < 64) {
        float v = 0.f;
#pragma unroll 8
        for (int r = 0; r < 128; r++) v += T[r * 65 + tid];
        atomicAdd(&g_stat2[tid], v);
    }
}

// ---------------- K7: sequential CSR segment-sum, no atomics ---------------
__global__ void __launch_bounds__(256) k7_seg(const float* __restrict__ gamma2,
                                              const float* __restrict__ beta2,
                                              float* __restrict__ out) {
    __shared__ float sS2[C], sT2[C];
    if (threadIdx.x < C) {
        int c = threadIdx.x;
        const float invE = 1.f / (float)N_EDGES;
        float mean = g_stat2[c] * invE;
        float var = g_stat2[32 + c] * invE - mean * mean;
        float s = gamma2[c] * rsqrtf(var + BN_EPS);
        sS2[c] = s;
        sT2[c] = beta2[c] - mean * s;
    }
    __syncthreads();
    int warp = threadIdx.x >> 5, lane = threadIdx.x & 31;
    int n = blockIdx.x * 8 + warp; // grid*8 = 50000 exact
    int start = g_off[n], end = g_off[n + 1];
    int w = lane & 15, half = lane >> 4;
    float sx = sS2[2 * w], sy = sS2[2 * w + 1];
    float tx = sT2[2 * w], ty = sT2[2 * w + 1];
    float ax = 0.f, ay = 0.f;
    const unsigned* Y = (const unsigned*)g_y2h; // 16 uints per edge row
    for (int p = start + half; p < end; p += 2) {
        unsigned v = Y[(size_t)p * 16 + w];     // sequential, coalesced
        float2 f = __half22float2(*(const __half2*)&v);
        ax += fmaxf(fmaf(f.x, sx, tx), 0.f);
        ay += fmaxf(fmaf(f.y, sy, ty), 0.f);
    }
    ax += __shfl_xor_sync(0xffffffffu, ax, 16);
    ay += __shfl_xor_sync(0xffffffffu, ay, 16);
    if (half == 0) {
        float2* o = (float2*)out;
        o[n * 16 + w] = make_float2(ax, ay);
    }
}

// ---------------- launch ----------------------------------------------------
extern "C" void kernel_launch(void* const* d_in, const int* in_sizes, int n_in,
                              void* d_out, int out_size) {
    const float* x      = (const float*)d_in[0];
    const float* W1     = (const float*)d_in[1];
    const float* b1     = (const float*)d_in[2];
    const float* gamma1 = (const float*)d_in[3];
    const float* beta1  = (const float*)d_in[4];
    const float* W2     = (const float*)d_in[5];
    const float* b2     = (const float*)d_in[6];
    const float* gamma2 = (const float*)d_in[7];
    const float* beta2  = (const float*)d_in[8];
    const int* ei       = (const int*)d_in[9];
    float* out = (float*)d_out;

    k1_node<<<N_NODES / 8, 256>>>(x, W1, b1);
    k2_stats1<<<2048, 256>>>(ei);
    kprefix<<<1, 1024>>>();
    k4_main<<<N_EDGES / 256, 128>>>(ei, W2, b2, gamma1, beta1);
    k7_seg<<<N_NODES / 8, 256>>>(gamma2, beta2, out);
}

// round 8
// speedup vs baseline: 1.6284x; 1.5142x over previous
#include <cuda_runtime.h>
#include <cuda_fp16.h>
#include <cstdint>

#define N_NODES 50000
#define N_EDGES 800000
#define C 32
#define BN_EPS 1e-5f

typedef unsigned long long ull;

// ---------------- device scratch ----------------
__device__ __align__(16) float g_A[N_NODES * C];
__device__ __align__(16) float g_B[N_NODES * C];
__device__ __align__(16) __half g_y2h[(size_t)N_EDGES * C]; // 51.2 MB fp16, edge order
__device__ float g_stat1[64];
__device__ float g_stat2[64];

__device__ __forceinline__ void red_add_v4(float* p, float a, float b, float c, float d) {
    asm volatile("red.global.add.v4.f32 [%0], {%1, %2, %3, %4};"
                 :: "l"(p), "f"(a), "f"(b), "f"(c), "f"(d) : "memory");
}
__device__ __forceinline__ ull pack2(float lo, float hi) {
    ull r; asm("mov.b64 %0, {%1, %2};" : "=l"(r) : "f"(lo), "f"(hi)); return r;
}
__device__ __forceinline__ float2 unpack2(ull v) {
    float2 f; asm("mov.b64 {%0, %1}, %2;" : "=f"(f.x), "=f"(f.y) : "l"(v)); return f;
}
__device__ __forceinline__ ull fma2(ull a, ull b, ull c) {
    ull d; asm("fma.rn.f32x2 %0, %1, %2, %3;" : "=l"(d) : "l"(a), "l"(b), "l"(c)); return d;
}

// ---------------- K1: zero out + stats + per-node precompute ---------------
__global__ void k1_node(const float* __restrict__ x, const float* __restrict__ W1,
                        const float* __restrict__ b1, float* __restrict__ out) {
    int g = blockIdx.x * blockDim.x + threadIdx.x;
    if (g < N_NODES * C) out[g] = 0.f;   // grid = 6250*256 = 1.6M = N_NODES*C
    if (g < 64) { g_stat1[g] = 0.f; g_stat2[g] = 0.f; }

    __shared__ float sW[2 * C * C];
    for (int i = threadIdx.x; i < 2 * C * C; i += blockDim.x) sW[i] = W1[i];
    __syncthreads();
    int warp = threadIdx.x >> 5, lane = threadIdx.x & 31;
    int node = blockIdx.x * (blockDim.x >> 5) + warp;
    if (node >= N_NODES) return;
    float xv = x[node * C + lane];
    float a = b1[lane], b = 0.f;
#pragma unroll
    for (int i = 0; i < C; i++) {
        float xi = __shfl_sync(0xffffffffu, xv, i);
        a = fmaf(xi, sW[i * C + lane], a);
        b = fmaf(xi, sW[(i + C) * C + lane], b);
    }
    g_A[node * C + lane] = a;
    g_B[node * C + lane] = b;
}

// ---------------- K2: stats1 of y1 = A[row]+B[col]; 8 lanes/edge -----------
__global__ void k2_stats1(const int* __restrict__ ei) {
    int g = blockIdx.x * blockDim.x + threadIdx.x;
    int nthr = gridDim.x * blockDim.x;
    int chunk = g & 7; // 4 channels [chunk*4, chunk*4+4)
    float s[4], q[4];
#pragma unroll
    for (int i = 0; i < 4; i++) { s[i] = 0.f; q[i] = 0.f; }
    const float4* A4 = (const float4*)g_A;
    const float4* B4 = (const float4*)g_B;
    for (int e = g >> 3; e < N_EDGES; e += nthr >> 3) {
        int row = ei[e];                 // broadcast across the 8-lane group
        int col = ei[N_EDGES + e];
        float4 a = A4[row * 8 + chunk];  // 1 wavefront per edge per table
        float4 b = B4[col * 8 + chunk];
        float y;
        y = a.x + b.x; s[0] += y; q[0] = fmaf(y, y, q[0]);
        y = a.y + b.y; s[1] += y; q[1] = fmaf(y, y, q[1]);
        y = a.z + b.z; s[2] += y; q[2] = fmaf(y, y, q[2]);
        y = a.w + b.w; s[3] += y; q[3] = fmaf(y, y, q[3]);
    }
#pragma unroll
    for (int off = 8; off < 32; off <<= 1) {
#pragma unroll
        for (int i = 0; i < 4; i++) {
            s[i] += __shfl_xor_sync(0xffffffffu, s[i], off);
            q[i] += __shfl_xor_sync(0xffffffffu, q[i], off);
        }
    }
    __shared__ float sh[64];
    if (threadIdx.x < 64) sh[threadIdx.x] = 0.f;
    __syncthreads();
    int lane = threadIdx.x & 31;
    if (lane < 8) {
#pragma unroll
        for (int i = 0; i < 4; i++) {
            atomicAdd(&sh[chunk * 4 + i], s[i]);
            atomicAdd(&sh[32 + chunk * 4 + i], q[i]);
        }
    }
    __syncthreads();
    if (threadIdx.x < 64) atomicAdd(&g_stat1[threadIdx.x], sh[threadIdx.x]);
}

// ---------------- K4: 8-lane gather -> SMEM -> 2-edge GEMM + fused stats2 --
#define HS 33
__global__ void __launch_bounds__(128, 4) k4_main(const int* __restrict__ ei,
                                                  const float* __restrict__ W2,
                                                  const float* __restrict__ b2,
                                                  const float* __restrict__ gamma1,
                                                  const float* __restrict__ beta1) {
    __shared__ __align__(16) float sW2[C * C];
    __shared__ float sh_h[256 * HS]; // h tile; reused for stats transpose
    __shared__ float sS1[C], sT1[C], sB2[C];
    int tid = threadIdx.x;
    for (int i = tid; i < C * C; i += blockDim.x) sW2[i] = W2[i];
    if (tid < C) {
        const float invE = 1.f / (float)N_EDGES;
        float mean = g_stat1[tid] * invE;
        float var = g_stat1[32 + tid] * invE - mean * mean;
        float s = gamma1[tid] * rsqrtf(var + BN_EPS);
        sS1[tid] = s;
        sT1[tid] = beta1[tid] - mean * s;
        sB2[tid] = b2[tid];
    }
    __syncthreads();

    // ---- phase 1: 8 lanes/edge gather (1 wavefront/edge/table) ----
    int q = tid & 7;                       // float4 slice 0..7
    const float4* A4 = (const float4*)g_A;
    const float4* B4 = (const float4*)g_B;
    float s1v[4], t1v[4];
#pragma unroll
    for (int j = 0; j < 4; j++) { s1v[j] = sS1[q * 4 + j]; t1v[j] = sT1[q * 4 + j]; }
#pragma unroll
    for (int r = 0; r < 16; r++) {
        int el = (tid >> 3) + r * 16;      // local edge 0..255
        int e = blockIdx.x * 256 + el;
        int row = ei[e];
        int col = ei[N_EDGES + e];
        float4 a = A4[row * 8 + q];
        float4 b = B4[col * 8 + q];
        float* hrow = sh_h + el * HS + q * 4;
        hrow[0] = fmaxf(fmaf(a.x + b.x, s1v[0], t1v[0]), 0.f);
        hrow[1] = fmaxf(fmaf(a.y + b.y, s1v[1], t1v[1]), 0.f);
        hrow[2] = fmaxf(fmaf(a.z + b.z, s1v[2], t1v[2]), 0.f);
        hrow[3] = fmaxf(fmaf(a.w + b.w, s1v[3], t1v[3]), 0.f);
    }
    __syncthreads();

    // ---- phase 2: 2 edges per thread, f32x2 GEMM ----
    ull accA[16], accB[16];
#pragma unroll
    for (int p = 0; p < 16; p++) {
        ull init = pack2(sB2[2 * p], sB2[2 * p + 1]);
        accA[p] = init; accB[p] = init;
    }
    const ulonglong2* W16 = (const ulonglong2*)sW2;
    const float* hA = sh_h + tid * HS;
    const float* hB = sh_h + (tid + 128) * HS;
#pragma unroll
    for (int i = 0; i < C; i++) {
        ull ha = pack2(hA[i], hA[i]);
        ull hb = pack2(hB[i], hB[i]);
#pragma unroll
        for (int qq = 0; qq < 8; qq++) {
            ulonglong2 w = W16[i * 8 + qq];
            accA[2 * qq]     = fma2(ha, w.x, accA[2 * qq]);
            accA[2 * qq + 1] = fma2(ha, w.y, accA[2 * qq + 1]);
            accB[2 * qq]     = fma2(hb, w.x, accB[2 * qq]);
            accB[2 * qq + 1] = fma2(hb, w.y, accB[2 * qq + 1]);
        }
    }

    // ---- sequential fp16 store + per-thread stats ----
    float s[32], sq[32];
    uint4 ovA[4], ovB[4];
    unsigned* owA = (unsigned*)ovA;
    unsigned* owB = (unsigned*)ovB;
#pragma unroll
    for (int p = 0; p < 16; p++) {
        float2 fA = unpack2(accA[p]);
        float2 fB = unpack2(accB[p]);
        __half2 hhA = __floats2half2_rn(fA.x, fA.y);
        __half2 hhB = __floats2half2_rn(fB.x, fB.y);
        owA[p] = *(unsigned*)&hhA;
        owB[p] = *(unsigned*)&hhB;
        s[2 * p]      = fA.x + fB.x;
        s[2 * p + 1]  = fA.y + fB.y;
        sq[2 * p]     = fmaf(fA.x, fA.x, fB.x * fB.x);
        sq[2 * p + 1] = fmaf(fA.y, fA.y, fB.y * fB.y);
    }
    size_t gA = (size_t)blockIdx.x * 256 + tid;
    size_t gB = gA + 128;
    uint4* Y = (uint4*)g_y2h;
#pragma unroll
    for (int p = 0; p < 4; p++) { Y[gA * 4 + p] = ovA[p]; Y[gB * 4 + p] = ovB[p]; }

    // ---- stats2 reduce via SMEM transpose (reuse sh_h; stride 65) ----
    __syncthreads();
    float* T = sh_h; // [128][65]: 8320 <= 8448 floats
#pragma unroll
    for (int j = 0; j < 32; j++) {
        T[tid * 65 + j] = s[j];
        T[tid * 65 + 32 + j] = sq[j];
    }
    __syncthreads();
    if (tid < 64) {
        float v = 0.f;
#pragma unroll 8
        for (int r = 0; r < 128; r++) v += T[r * 65 + tid];
        atomicAdd(&g_stat2[tid], v);
    }
}

// ---------------- K7: BN2+ReLU + vector atomic scatter ---------------------
__global__ void __launch_bounds__(256) k7_scatter(const int* __restrict__ ei,
                                                  const float* __restrict__ gamma2,
                                                  const float* __restrict__ beta2,
                                                  float* __restrict__ out) {
    __shared__ float sS2[C], sT2[C];
    if (threadIdx.x < C) {
        int c = threadIdx.x;
        const float invE = 1.f / (float)N_EDGES;
        float mean = g_stat2[c] * invE;
        float var = g_stat2[32 + c] * invE - mean * mean;
        float s = gamma2[c] * rsqrtf(var + BN_EPS);
        sS2[c] = s;
        sT2[c] = beta2[c] - mean * s;
    }
    __syncthreads();
    int g = blockIdx.x * blockDim.x + threadIdx.x; // grid = E*4/256
    int e = g >> 2;
    int chunk = g & 3; // 8 channels
    int row = ei[e];
    const uint4* Y = (const uint4*)g_y2h;
    uint4 v = Y[(size_t)e * 4 + chunk];
    const unsigned* w = (const unsigned*)&v;
    float h[8];
#pragma unroll
    for (int p = 0; p < 4; p++) {
        float2 f = __half22float2(*(const __half2*)&w[p]);
        int c = chunk * 8 + 2 * p;
        h[2 * p]     = fmaxf(fmaf(f.x, sS2[c],     sT2[c]),     0.f);
        h[2 * p + 1] = fmaxf(fmaf(f.y, sS2[c + 1], sT2[c + 1]), 0.f);
    }
    float* dst = out + row * C + chunk * 8;
    red_add_v4(dst,     h[0], h[1], h[2], h[3]);
    red_add_v4(dst + 4, h[4], h[5], h[6], h[7]);
}

// ---------------- launch ----------------------------------------------------
extern "C" void kernel_launch(void* const* d_in, const int* in_sizes, int n_in,
                              void* d_out, int out_size) {
    const float* x      = (const float*)d_in[0];
    const float* W1     = (const float*)d_in[1];
    const float* b1     = (const float*)d_in[2];
    const float* gamma1 = (const float*)d_in[3];
    const float* beta1  = (const float*)d_in[4];
    const float* W2     = (const float*)d_in[5];
    const float* b2     = (const float*)d_in[6];
    const float* gamma2 = (const float*)d_in[7];
    const float* beta2  = (const float*)d_in[8];
    const int* ei       = (const int*)d_in[9];
    float* out = (float*)d_out;

    k1_node<<<N_NODES / 8, 256>>>(x, W1, b1, out);
    k2_stats1<<<2048, 256>>>(ei);
    k4_main<<<N_EDGES / 256, 128>>>(ei, W2, b2, gamma1, beta1);
    k7_scatter<<<N_EDGES * 4 / 256, 256>>>(ei, gamma2, beta2, out);
}

// round 9
// speedup vs baseline: 1.9008x; 1.1672x over previous
#include <cuda_runtime.h>
#include <cuda_fp16.h>
#include <cstdint>

#define N_NODES 50000
#define N_EDGES 800000
#define C 32
#define BN_EPS 1e-5f

typedef unsigned long long ull;

// ---------------- device scratch ----------------
__device__ __align__(16) float g_A[N_NODES * C];
__device__ __align__(16) float g_B[N_NODES * C];
__device__ __align__(16) __half g_y2h[(size_t)N_EDGES * C]; // 51.2 MB fp16, edge order
__device__ float g_stat1[64];
__device__ float g_stat2[64];

__device__ __forceinline__ void red_add_v4(float* p, float a, float b, float c, float d) {
    asm volatile("red.global.add.v4.f32 [%0], {%1, %2, %3, %4};"
                 :: "l"(p), "f"(a), "f"(b), "f"(c), "f"(d) : "memory");
}
__device__ __forceinline__ unsigned h2_bits(__half2 h) { return *(unsigned*)&h; }

// ---------------- K1: zero out + stats + per-node precompute ---------------
__global__ void k1_node(const float* __restrict__ x, const float* __restrict__ W1,
                        const float* __restrict__ b1, float* __restrict__ out) {
    int g = blockIdx.x * blockDim.x + threadIdx.x;
    if (g < N_NODES * C) out[g] = 0.f;   // grid = 6250*256 = 1.6M = N_NODES*C
    if (g < 64) { g_stat1[g] = 0.f; g_stat2[g] = 0.f; }

    __shared__ float sW[2 * C * C];
    for (int i = threadIdx.x; i < 2 * C * C; i += blockDim.x) sW[i] = W1[i];
    __syncthreads();
    int warp = threadIdx.x >> 5, lane = threadIdx.x & 31;
    int node = blockIdx.x * (blockDim.x >> 5) + warp;
    if (node >= N_NODES) return;
    float xv = x[node * C + lane];
    float a = b1[lane], b = 0.f;
#pragma unroll
    for (int i = 0; i < C; i++) {
        float xi = __shfl_sync(0xffffffffu, xv, i);
        a = fmaf(xi, sW[i * C + lane], a);
        b = fmaf(xi, sW[(i + C) * C + lane], b);
    }
    g_A[node * C + lane] = a;
    g_B[node * C + lane] = b;
}

// ---------------- K2: stats1 of y1 = A[row]+B[col]; 8 lanes/edge -----------
__global__ void k2_stats1(const int* __restrict__ ei) {
    int g = blockIdx.x * blockDim.x + threadIdx.x;
    int nthr = gridDim.x * blockDim.x;
    int chunk = g & 7; // 4 channels [chunk*4, chunk*4+4)
    float s[4], q[4];
#pragma unroll
    for (int i = 0; i < 4; i++) { s[i] = 0.f; q[i] = 0.f; }
    const float4* A4 = (const float4*)g_A;
    const float4* B4 = (const float4*)g_B;
    for (int e = g >> 3; e < N_EDGES; e += nthr >> 3) {
        int row = ei[e];
        int col = ei[N_EDGES + e];
        float4 a = A4[row * 8 + chunk];
        float4 b = B4[col * 8 + chunk];
        float y;
        y = a.x + b.x; s[0] += y; q[0] = fmaf(y, y, q[0]);
        y = a.y + b.y; s[1] += y; q[1] = fmaf(y, y, q[1]);
        y = a.z + b.z; s[2] += y; q[2] = fmaf(y, y, q[2]);
        y = a.w + b.w; s[3] += y; q[3] = fmaf(y, y, q[3]);
    }
#pragma unroll
    for (int off = 8; off < 32; off <<= 1) {
#pragma unroll
        for (int i = 0; i < 4; i++) {
            s[i] += __shfl_xor_sync(0xffffffffu, s[i], off);
            q[i] += __shfl_xor_sync(0xffffffffu, q[i], off);
        }
    }
    __shared__ float sh[64];
    if (threadIdx.x < 64) sh[threadIdx.x] = 0.f;
    __syncthreads();
    int lane = threadIdx.x & 31;
    if (lane < 8) {
#pragma unroll
        for (int i = 0; i < 4; i++) {
            atomicAdd(&sh[chunk * 4 + i], s[i]);
            atomicAdd(&sh[32 + chunk * 4 + i], q[i]);
        }
    }
    __syncthreads();
    if (threadIdx.x < 64) atomicAdd(&g_stat1[threadIdx.x], sh[threadIdx.x]);
}

// ---------------- K4: gather -> fp16 SMEM -> tensor-core GEMM + stats2 -----
#define HT 40  // fp16 h-tile stride (halves): 20r+c banks conflict-free
__global__ void __launch_bounds__(128, 4) k4_main(const int* __restrict__ ei,
                                                  const float* __restrict__ W2,
                                                  const float* __restrict__ b2,
                                                  const float* __restrict__ gamma1,
                                                  const float* __restrict__ beta1) {
    __shared__ __half sh_h[256 * HT];   // 20.5 KB
    __shared__ __half sWT[C * C];       // W2^T fp16 [n][k]
    __shared__ float sS1[C], sT1[C];
    __shared__ float sStat[4 * 64];
    int tid = threadIdx.x;

    // prologue: W2^T -> fp16, BN1 fold
    for (int i = tid; i < C * C; i += 128) {
        int k = i >> 5, n = i & 31;
        sWT[n * C + k] = __float2half(W2[i]);
    }
    if (tid < C) {
        const float invE = 1.f / (float)N_EDGES;
        float mean = g_stat1[tid] * invE;
        float var = g_stat1[32 + tid] * invE - mean * mean;
        float s = gamma1[tid] * rsqrtf(var + BN_EPS);
        sS1[tid] = s;
        sT1[tid] = beta1[tid] - mean * s;
    }
    __syncthreads();

    // ---- phase 1: 8 lanes/edge gather + BN1 + ReLU -> fp16 tile ----
    int q = tid & 7;
    const float4* A4 = (const float4*)g_A;
    const float4* B4 = (const float4*)g_B;
    float s1v[4], t1v[4];
#pragma unroll
    for (int j = 0; j < 4; j++) { s1v[j] = sS1[q * 4 + j]; t1v[j] = sT1[q * 4 + j]; }
#pragma unroll
    for (int r = 0; r < 16; r++) {
        int el = (tid >> 3) + r * 16;
        int e = blockIdx.x * 256 + el;
        int row = ei[e];
        int col = ei[N_EDGES + e];
        float4 a = A4[row * 8 + q];
        float4 b = B4[col * 8 + q];
        float h0 = fmaxf(fmaf(a.x + b.x, s1v[0], t1v[0]), 0.f);
        float h1 = fmaxf(fmaf(a.y + b.y, s1v[1], t1v[1]), 0.f);
        float h2 = fmaxf(fmaf(a.z + b.z, s1v[2], t1v[2]), 0.f);
        float h3 = fmaxf(fmaf(a.w + b.w, s1v[3], t1v[3]), 0.f);
        __half2 p01 = __floats2half2_rn(h0, h1);
        __half2 p23 = __floats2half2_rn(h2, h3);
        *(uint2*)(&sh_h[el * HT + q * 4]) = make_uint2(h2_bits(p01), h2_bits(p23));
    }
    __syncthreads();

    // ---- phase 2: tensor-core GEMM. warp w: edges [64w, 64w+64) ----
    int w = tid >> 5, l = tid & 31;
    int lq = l & 3, lr = l >> 2;

    // B fragments (resident for whole phase): b[nt][kk][2]
    unsigned bfr[4][2][2];
#pragma unroll
    for (int nt = 0; nt < 4; nt++)
#pragma unroll
        for (int kk = 0; kk < 2; kk++) {
            const __half* base = sWT + (lr + 8 * nt) * C + 2 * lq + 16 * kk;
            bfr[nt][kk][0] = *(const unsigned*)(base);
            bfr[nt][kk][1] = *(const unsigned*)(base + 8);
        }
    // D fragments init with bias
    float d[4][4][4];
#pragma unroll
    for (int nt = 0; nt < 4; nt++) {
        float bx = b2[2 * lq + 8 * nt];
        float by = b2[2 * lq + 8 * nt + 1];
#pragma unroll
        for (int mt = 0; mt < 4; mt++) {
            d[mt][nt][0] = bx; d[mt][nt][1] = by;
            d[mt][nt][2] = bx; d[mt][nt][3] = by;
        }
    }
#pragma unroll
    for (int mt = 0; mt < 4; mt++) {
        int r0 = w * 64 + mt * 16 + lr;
#pragma unroll
        for (int kk = 0; kk < 2; kk++) {
            unsigned a0 = *(const unsigned*)(&sh_h[r0 * HT + 2 * lq + 16 * kk]);
            unsigned a1 = *(const unsigned*)(&sh_h[(r0 + 8) * HT + 2 * lq + 16 * kk]);
            unsigned a2 = *(const unsigned*)(&sh_h[r0 * HT + 2 * lq + 8 + 16 * kk]);
            unsigned a3 = *(const unsigned*)(&sh_h[(r0 + 8) * HT + 2 * lq + 8 + 16 * kk]);
#pragma unroll
            for (int nt = 0; nt < 4; nt++) {
                asm volatile(
                    "mma.sync.aligned.m16n8k16.row.col.f32.f16.f16.f32 "
                    "{%0,%1,%2,%3}, {%4,%5,%6,%7}, {%8,%9}, {%0,%1,%2,%3};"
                    : "+f"(d[mt][nt][0]), "+f"(d[mt][nt][1]),
                      "+f"(d[mt][nt][2]), "+f"(d[mt][nt][3])
                    : "r"(a0), "r"(a1), "r"(a2), "r"(a3),
                      "r"(bfr[nt][kk][0]), "r"(bfr[nt][kk][1]));
            }
        }
    }

    // ---- store y2 (fp16) directly from frags + per-lane stats ----
    size_t ebase = (size_t)blockIdx.x * 256 + w * 64;
    float sv[4][2], qv[4][2];
#pragma unroll
    for (int nt = 0; nt < 4; nt++) { sv[nt][0] = sv[nt][1] = qv[nt][0] = qv[nt][1] = 0.f; }
#pragma unroll
    for (int mt = 0; mt < 4; mt++) {
        size_t row0 = ebase + mt * 16 + lr;
        size_t row1 = row0 + 8;
#pragma unroll
        for (int nt = 0; nt < 4; nt++) {
            float d0 = d[mt][nt][0], d1 = d[mt][nt][1];
            float d2 = d[mt][nt][2], d3 = d[mt][nt][3];
            __half2 ph0 = __floats2half2_rn(d0, d1);
            __half2 ph1 = __floats2half2_rn(d2, d3);
            int cw = 2 * lq + 8 * nt;
            *(unsigned*)(g_y2h + row0 * C + cw) = h2_bits(ph0);
            *(unsigned*)(g_y2h + row1 * C + cw) = h2_bits(ph1);
            sv[nt][0] += d0 + d2;              qv[nt][0] += d0 * d0 + d2 * d2;
            sv[nt][1] += d1 + d3;              qv[nt][1] += d1 * d1 + d3 * d3;
        }
    }
    // reduce over the 8 row-group lanes (same lq share columns)
#pragma unroll
    for (int off = 4; off < 32; off <<= 1) {
#pragma unroll
        for (int nt = 0; nt < 4; nt++)
#pragma unroll
            for (int j = 0; j < 2; j++) {
                sv[nt][j] += __shfl_xor_sync(0xffffffffu, sv[nt][j], off);
                qv[nt][j] += __shfl_xor_sync(0xffffffffu, qv[nt][j], off);
            }
    }
    if (lr == 0) {
#pragma unroll
        for (int nt = 0; nt < 4; nt++)
#pragma unroll
            for (int j = 0; j < 2; j++) {
                int c = 2 * lq + 8 * nt + j;
                sStat[w * 64 + c] = sv[nt][j];
                sStat[w * 64 + 32 + c] = qv[nt][j];
            }
    }
    __syncthreads();
    if (tid < 64)
        atomicAdd(&g_stat2[tid],
                  sStat[tid] + sStat[64 + tid] + sStat[128 + tid] + sStat[192 + tid]);
}

// ---------------- K7: BN2+ReLU + vector atomic scatter ---------------------
__global__ void __launch_bounds__(256) k7_scatter(const int* __restrict__ ei,
                                                  const float* __restrict__ gamma2,
                                                  const float* __restrict__ beta2,
                                                  float* __restrict__ out) {
    __shared__ float sS2[C], sT2[C];
    if (threadIdx.x < C) {
        int c = threadIdx.x;
        const float invE = 1.f / (float)N_EDGES;
        float mean = g_stat2[c] * invE;
        float var = g_stat2[32 + c] * invE - mean * mean;
        float s = gamma2[c] * rsqrtf(var + BN_EPS);
        sS2[c] = s;
        sT2[c] = beta2[c] - mean * s;
    }
    __syncthreads();
    int g = blockIdx.x * blockDim.x + threadIdx.x; // grid = E*4/256
    int e = g >> 2;
    int chunk = g & 3; // 8 channels
    int row = ei[e];
    const uint4* Y = (const uint4*)g_y2h;
    uint4 v = Y[(size_t)e * 4 + chunk];
    const unsigned* w = (const unsigned*)&v;
    float h[8];
#pragma unroll
    for (int p = 0; p < 4; p++) {
        float2 f = __half22float2(*(const __half2*)&w[p]);
        int c = chunk * 8 + 2 * p;
        h[2 * p]     = fmaxf(fmaf(f.x, sS2[c],     sT2[c]),     0.f);
        h[2 * p + 1] = fmaxf(fmaf(f.y, sS2[c + 1], sT2[c + 1]), 0.f);
    }
    float* dst = out + row * C + chunk * 8;
    red_add_v4(dst,     h[0], h[1], h[2], h[3]);
    red_add_v4(dst + 4, h[4], h[5], h[6], h[7]);
}

// ---------------- launch ----------------------------------------------------
extern "C" void kernel_launch(void* const* d_in, const int* in_sizes, int n_in,
                              void* d_out, int out_size) {
    const float* x      = (const float*)d_in[0];
    const float* W1     = (const float*)d_in[1];
    const float* b1     = (const float*)d_in[2];
    const float* gamma1 = (const float*)d_in[3];
    const float* beta1  = (const float*)d_in[4];
    const float* W2     = (const float*)d_in[5];
    const float* b2     = (const float*)d_in[6];
    const float* gamma2 = (const float*)d_in[7];
    const float* beta2  = (const float*)d_in[8];
    const int* ei       = (const int*)d_in[9];
    float* out = (float*)d_out;

    k1_node<<<N_NODES / 8, 256>>>(x, W1, b1, out);
    k2_stats1<<<2048, 256>>>(ei);
    k4_main<<<N_EDGES / 256, 128>>>(ei, W2, b2, gamma1, beta1);
    k7_scatter<<<N_EDGES * 4 / 256, 256>>>(ei, gamma2, beta2, out);
}

// round 10
// speedup vs baseline: 2.0003x; 1.0524x over previous
#include <cuda_runtime.h>
#include <cuda_fp16.h>
#include <cstdint>

#define N_NODES 50000
#define N_EDGES 800000
#define C 32
#define BN_EPS 1e-5f

typedef unsigned long long ull;

// ---------------- device scratch ----------------
__device__ __align__(16) __half g_Ah[N_NODES * C];          // x@W1_top + b1 (fp16)
__device__ __align__(16) __half g_Bh[N_NODES * C];          // x@W1_bot (fp16)
__device__ __align__(16) __half g_y2h[(size_t)N_EDGES * C]; // 51.2 MB fp16, edge order
__device__ float g_stat1[64];
__device__ float g_stat2[64];

__device__ __forceinline__ void red_add_v4(float* p, float a, float b, float c, float d) {
    asm volatile("red.global.add.v4.f32 [%0], {%1, %2, %3, %4};"
                 :: "l"(p), "f"(a), "f"(b), "f"(c), "f"(d) : "memory");
}
__device__ __forceinline__ unsigned h2_bits(__half2 h) { return *(unsigned*)&h; }

// ---------------- K1: zero out + stats + per-node precompute ---------------
__global__ void k1_node(const float* __restrict__ x, const float* __restrict__ W1,
                        const float* __restrict__ b1, float* __restrict__ out) {
    int g = blockIdx.x * blockDim.x + threadIdx.x;
    if (g < N_NODES * C) out[g] = 0.f;   // grid = 6250*256 = 1.6M = N_NODES*C
    if (g < 64) { g_stat1[g] = 0.f; g_stat2[g] = 0.f; }

    __shared__ float sW[2 * C * C];
    for (int i = threadIdx.x; i < 2 * C * C; i += blockDim.x) sW[i] = W1[i];
    __syncthreads();
    int warp = threadIdx.x >> 5, lane = threadIdx.x & 31;
    int node = blockIdx.x * (blockDim.x >> 5) + warp;
    if (node >= N_NODES) return;
    float xv = x[node * C + lane];
    float a = b1[lane], b = 0.f;
#pragma unroll
    for (int i = 0; i < C; i++) {
        float xi = __shfl_sync(0xffffffffu, xv, i);
        a = fmaf(xi, sW[i * C + lane], a);
        b = fmaf(xi, sW[(i + C) * C + lane], b);
    }
    g_Ah[node * C + lane] = __float2half(a);
    g_Bh[node * C + lane] = __float2half(b);
}

// ---------------- K2: stats1 of y1 = A[row]+B[col]; fp16 gather ------------
__global__ void k2_stats1(const int* __restrict__ ei) {
    int g = blockIdx.x * blockDim.x + threadIdx.x;
    int nthr = gridDim.x * blockDim.x;
    int chunk = g & 7; // 4 channels [chunk*4, chunk*4+4)
    float s[4], q[4];
#pragma unroll
    for (int i = 0; i < 4; i++) { s[i] = 0.f; q[i] = 0.f; }
    const uint2* A2 = (const uint2*)g_Ah;  // node row = 8 uint2 (64B)
    const uint2* B2 = (const uint2*)g_Bh;
    for (int e = g >> 3; e < N_EDGES; e += nthr >> 3) {
        int row = ei[e];
        int col = ei[N_EDGES + e];
        uint2 av = A2[row * 8 + chunk];
        uint2 bv = B2[col * 8 + chunk];
        float2 a0 = __half22float2(*(const __half2*)&av.x);
        float2 a1 = __half22float2(*(const __half2*)&av.y);
        float2 b0 = __half22float2(*(const __half2*)&bv.x);
        float2 b1 = __half22float2(*(const __half2*)&bv.y);
        float y;
        y = a0.x + b0.x; s[0] += y; q[0] = fmaf(y, y, q[0]);
        y = a0.y + b0.y; s[1] += y; q[1] = fmaf(y, y, q[1]);
        y = a1.x + b1.x; s[2] += y; q[2] = fmaf(y, y, q[2]);
        y = a1.y + b1.y; s[3] += y; q[3] = fmaf(y, y, q[3]);
    }
#pragma unroll
    for (int off = 8; off < 32; off <<= 1) {
#pragma unroll
        for (int i = 0; i < 4; i++) {
            s[i] += __shfl_xor_sync(0xffffffffu, s[i], off);
            q[i] += __shfl_xor_sync(0xffffffffu, q[i], off);
        }
    }
    __shared__ float sh[64];
    if (threadIdx.x < 64) sh[threadIdx.x] = 0.f;
    __syncthreads();
    int lane = threadIdx.x & 31;
    if (lane < 8) {
#pragma unroll
        for (int i = 0; i < 4; i++) {
            atomicAdd(&sh[chunk * 4 + i], s[i]);
            atomicAdd(&sh[32 + chunk * 4 + i], q[i]);
        }
    }
    __syncthreads();
    if (threadIdx.x < 64) atomicAdd(&g_stat1[threadIdx.x], sh[threadIdx.x]);
}

// ---------------- K4: fp16 gather -> fp16 SMEM -> tensor GEMM + stats2 -----
#define HT 40  // fp16 h-tile stride (halves)
__global__ void __launch_bounds__(128, 4) k4_main(const int* __restrict__ ei,
                                                  const float* __restrict__ W2,
                                                  const float* __restrict__ b2,
                                                  const float* __restrict__ gamma1,
                                                  const float* __restrict__ beta1) {
    __shared__ __half sh_h[256 * HT];   // 20.5 KB
    __shared__ __half sWT[C * C];       // W2^T fp16 [n][k]
    __shared__ float sS1[C], sT1[C];
    __shared__ float sStat[4 * 64];
    int tid = threadIdx.x;

    // prologue: W2^T -> fp16, BN1 fold
    for (int i = tid; i < C * C; i += 128) {
        int k = i >> 5, n = i & 31;
        sWT[n * C + k] = __float2half(W2[i]);
    }
    if (tid < C) {
        const float invE = 1.f / (float)N_EDGES;
        float mean = g_stat1[tid] * invE;
        float var = g_stat1[32 + tid] * invE - mean * mean;
        float s = gamma1[tid] * rsqrtf(var + BN_EPS);
        sS1[tid] = s;
        sT1[tid] = beta1[tid] - mean * s;
    }
    __syncthreads();

    // ---- phase 1: 8 lanes/edge fp16 gather + BN1 + ReLU -> fp16 tile ----
    int q = tid & 7;
    const uint2* A2 = (const uint2*)g_Ah;
    const uint2* B2 = (const uint2*)g_Bh;
    float s1v[4], t1v[4];
#pragma unroll
    for (int j = 0; j < 4; j++) { s1v[j] = sS1[q * 4 + j]; t1v[j] = sT1[q * 4 + j]; }
#pragma unroll
    for (int r = 0; r < 16; r++) {
        int el = (tid >> 3) + r * 16;
        int e = blockIdx.x * 256 + el;
        int row = ei[e];
        int col = ei[N_EDGES + e];
        uint2 av = A2[row * 8 + q];
        uint2 bv = B2[col * 8 + q];
        float2 a0 = __half22float2(*(const __half2*)&av.x);
        float2 a1 = __half22float2(*(const __half2*)&av.y);
        float2 b0 = __half22float2(*(const __half2*)&bv.x);
        float2 b1 = __half22float2(*(const __half2*)&bv.y);
        float h0 = fmaxf(fmaf(a0.x + b0.x, s1v[0], t1v[0]), 0.f);
        float h1 = fmaxf(fmaf(a0.y + b0.y, s1v[1], t1v[1]), 0.f);
        float h2 = fmaxf(fmaf(a1.x + b1.x, s1v[2], t1v[2]), 0.f);
        float h3 = fmaxf(fmaf(a1.y + b1.y, s1v[3], t1v[3]), 0.f);
        __half2 p01 = __floats2half2_rn(h0, h1);
        __half2 p23 = __floats2half2_rn(h2, h3);
        *(uint2*)(&sh_h[el * HT + q * 4]) = make_uint2(h2_bits(p01), h2_bits(p23));
    }
    __syncthreads();

    // ---- phase 2: tensor-core GEMM. warp w: edges [64w, 64w+64) ----
    int w = tid >> 5, l = tid & 31;
    int lq = l & 3, lr = l >> 2;

    unsigned bfr[4][2][2];
#pragma unroll
    for (int nt = 0; nt < 4; nt++)
#pragma unroll
        for (int kk = 0; kk < 2; kk++) {
            const __half* base = sWT + (lr + 8 * nt) * C + 2 * lq + 16 * kk;
            bfr[nt][kk][0] = *(const unsigned*)(base);
            bfr[nt][kk][1] = *(const unsigned*)(base + 8);
        }
    float d[4][4][4];
#pragma unroll
    for (int nt = 0; nt < 4; nt++) {
        float bx = b2[2 * lq + 8 * nt];
        float by = b2[2 * lq + 8 * nt + 1];
#pragma unroll
        for (int mt = 0; mt < 4; mt++) {
            d[mt][nt][0] = bx; d[mt][nt][1] = by;
            d[mt][nt][2] = bx; d[mt][nt][3] = by;
        }
    }
#pragma unroll
    for (int mt = 0; mt < 4; mt++) {
        int r0 = w * 64 + mt * 16 + lr;
#pragma unroll
        for (int kk = 0; kk < 2; kk++) {
            unsigned a0 = *(const unsigned*)(&sh_h[r0 * HT + 2 * lq + 16 * kk]);
            unsigned a1 = *(const unsigned*)(&sh_h[(r0 + 8) * HT + 2 * lq + 16 * kk]);
            unsigned a2 = *(const unsigned*)(&sh_h[r0 * HT + 2 * lq + 8 + 16 * kk]);
            unsigned a3 = *(const unsigned*)(&sh_h[(r0 + 8) * HT + 2 * lq + 8 + 16 * kk]);
#pragma unroll
            for (int nt = 0; nt < 4; nt++) {
                asm volatile(
                    "mma.sync.aligned.m16n8k16.row.col.f32.f16.f16.f32 "
                    "{%0,%1,%2,%3}, {%4,%5,%6,%7}, {%8,%9}, {%0,%1,%2,%3};"
                    : "+f"(d[mt][nt][0]), "+f"(d[mt][nt][1]),
                      "+f"(d[mt][nt][2]), "+f"(d[mt][nt][3])
                    : "r"(a0), "r"(a1), "r"(a2), "r"(a3),
                      "r"(bfr[nt][kk][0]), "r"(bfr[nt][kk][1]));
            }
        }
    }

    // ---- store y2 (fp16) directly from frags + per-lane stats ----
    size_t ebase = (size_t)blockIdx.x * 256 + w * 64;
    float sv[4][2], qv[4][2];
#pragma unroll
    for (int nt = 0; nt < 4; nt++) { sv[nt][0] = sv[nt][1] = qv[nt][0] = qv[nt][1] = 0.f; }
#pragma unroll
    for (int mt = 0; mt < 4; mt++) {
        size_t row0 = ebase + mt * 16 + lr;
        size_t row1 = row0 + 8;
#pragma unroll
        for (int nt = 0; nt < 4; nt++) {
            float d0 = d[mt][nt][0], d1 = d[mt][nt][1];
            float d2 = d[mt][nt][2], d3 = d[mt][nt][3];
            __half2 ph0 = __floats2half2_rn(d0, d1);
            __half2 ph1 = __floats2half2_rn(d2, d3);
            int cw = 2 * lq + 8 * nt;
            *(unsigned*)(g_y2h + row0 * C + cw) = h2_bits(ph0);
            *(unsigned*)(g_y2h + row1 * C + cw) = h2_bits(ph1);
            sv[nt][0] += d0 + d2;              qv[nt][0] += d0 * d0 + d2 * d2;
            sv[nt][1] += d1 + d3;              qv[nt][1] += d1 * d1 + d3 * d3;
        }
    }
#pragma unroll
    for (int off = 4; off < 32; off <<= 1) {
#pragma unroll
        for (int nt = 0; nt < 4; nt++)
#pragma unroll
            for (int j = 0; j < 2; j++) {
                sv[nt][j] += __shfl_xor_sync(0xffffffffu, sv[nt][j], off);
                qv[nt][j] += __shfl_xor_sync(0xffffffffu, qv[nt][j], off);
            }
    }
    if (lr == 0) {
#pragma unroll
        for (int nt = 0; nt < 4; nt++)
#pragma unroll
            for (int j = 0; j < 2; j++) {
                int c = 2 * lq + 8 * nt + j;
                sStat[w * 64 + c] = sv[nt][j];
                sStat[w * 64 + 32 + c] = qv[nt][j];
            }
    }
    __syncthreads();
    if (tid < 64)
        atomicAdd(&g_stat2[tid],
                  sStat[tid] + sStat[64 + tid] + sStat[128 + tid] + sStat[192 + tid]);
}

// ---------------- K7: BN2+ReLU + vector atomic scatter ---------------------
__global__ void __launch_bounds__(256) k7_scatter(const int* __restrict__ ei,
                                                  const float* __restrict__ gamma2,
                                                  const float* __restrict__ beta2,
                                                  float* __restrict__ out) {
    __shared__ float sS2[C], sT2[C];
    if (threadIdx.x < C) {
        int c = threadIdx.x;
        const float invE = 1.f / (float)N_EDGES;
        float mean = g_stat2[c] * invE;
        float var = g_stat2[32 + c] * invE - mean * mean;
        float s = gamma2[c] * rsqrtf(var + BN_EPS);
        sS2[c] = s;
        sT2[c] = beta2[c] - mean * s;
    }
    __syncthreads();
    int g = blockIdx.x * blockDim.x + threadIdx.x; // grid = E*4/256
    int e = g >> 2;
    int chunk = g & 3; // 8 channels
    int row = ei[e];
    const uint4* Y = (const uint4*)g_y2h;
    uint4 v = Y[(size_t)e * 4 + chunk];
    const unsigned* w = (const unsigned*)&v;
    float h[8];
#pragma unroll
    for (int p = 0; p < 4; p++) {
        float2 f = __half22float2(*(const __half2*)&w[p]);
        int c = chunk * 8 + 2 * p;
        h[2 * p]     = fmaxf(fmaf(f.x, sS2[c],     sT2[c]),     0.f);
        h[2 * p + 1] = fmaxf(fmaf(f.y, sS2[c + 1], sT2[c + 1]), 0.f);
    }
    float* dst = out + row * C + chunk * 8;
    red_add_v4(dst,     h[0], h[1], h[2], h[3]);
    red_add_v4(dst + 4, h[4], h[5], h[6], h[7]);
}

// ---------------- launch ----------------------------------------------------
extern "C" void kernel_launch(void* const* d_in, const int* in_sizes, int n_in,
                              void* d_out, int out_size) {
    const float* x      = (const float*)d_in[0];
    const float* W1     = (const float*)d_in[1];
    const float* b1     = (const float*)d_in[2];
    const float* gamma1 = (const float*)d_in[3];
    const float* beta1  = (const float*)d_in[4];
    const float* W2     = (const float*)d_in[5];
    const float* b2     = (const float*)d_in[6];
    const float* gamma2 = (const float*)d_in[7];
    const float* beta2  = (const float*)d_in[8];
    const int* ei       = (const int*)d_in[9];
    float* out = (float*)d_out;

    k1_node<<<N_NODES / 8, 256>>>(x, W1, b1, out);
    k2_stats1<<<2048, 256>>>(ei);
    k4_main<<<N_EDGES / 256, 128>>>(ei, W2, b2, gamma1, beta1);
    k7_scatter<<<N_EDGES * 4 / 256, 256>>>(ei, gamma2, beta2, out);
}